// round 4
// baseline (speedup 1.0000x reference)
#include <cuda_runtime.h>

#define B_ 256
#define S_ 196
#define R_ 1024
#define H_ 512

#define KSPLIT 4
#define KCHUNK (R_ / KSPLIT)
#define NSPOOL 4
#define SCHUNK (S_ / NSPOOL)   // 49

#define NTHREADS 256

// Scratch (no allocations allowed anywhere)
__device__ float g_att_h_part[KSPLIT * B_ * H_];
__device__ float g_scores[B_ * S_];
__device__ float g_pool_part[NSPOOL * B_ * R_];

// Grid barrier state. Generation-based: never needs resetting across launches.
__device__ unsigned g_bar_count;            // zero-init, returned to 0 each barrier
__device__ volatile unsigned g_bar_gen;     // monotonically increasing

__device__ __forceinline__ float tanh_fast(float x) {
    float y;
    asm("tanh.approx.f32 %0, %1;" : "=f"(y) : "f"(x));
    return y;
}

__device__ __forceinline__ void grid_barrier() {
    __syncthreads();
    if (threadIdx.x == 0) {
        __threadfence();                          // release prior writes
        unsigned gen = g_bar_gen;
        if (atomicAdd(&g_bar_count, 1u) == gridDim.x - 1) {
            g_bar_count = 0;
            __threadfence();
            g_bar_gen = gen + 1;                  // release
        } else {
            while (g_bar_gen == gen) __nanosleep(64);
        }
        __threadfence();                          // acquire
    }
    __syncthreads();
}

// ---------------------------------------------------------------------------
// Phase 0: partial att_h GEMM. 512 items: (hx 16) x (by 8) x (z 4).
// ---------------------------------------------------------------------------
__device__ void phase_h2att(char* smem,
                            const float* __restrict__ hidden,
                            const float* __restrict__ W,
                            const float* __restrict__ bias) {
    float (*As)[33] = (float (*)[33])smem;
    float (*Bs)[33] = (float (*)[33])(smem + 32 * 33 * sizeof(float));
    const int tid = threadIdx.x;
    const int tx = tid & 15;
    const int ty = tid >> 4;
    const int nitems = 16 * 8 * KSPLIT;

    for (int item = blockIdx.x; item < nitems; item += gridDim.x) {
        const int h0 = (item & 15) * 32;
        const int b0 = ((item >> 4) & 7) * 32;
        const int z  = item >> 7;
        float acc00 = 0.f, acc01 = 0.f, acc10 = 0.f, acc11 = 0.f;

        const int kbeg = z * KCHUNK;
        for (int k0 = kbeg; k0 < kbeg + KCHUNK; k0 += 32) {
            #pragma unroll
            for (int i = 0; i < 4; i++) {
                int idx = tid + i * 256;
                int r = idx >> 5, c = idx & 31;
                As[r][c] = hidden[(size_t)(b0 + r) * R_ + k0 + c];
                Bs[r][c] = W[(size_t)(h0 + r) * R_ + k0 + c];
            }
            __syncthreads();
            #pragma unroll
            for (int kk = 0; kk < 32; kk++) {
                float a0 = As[ty][kk],      a1 = As[ty + 16][kk];
                float w0 = Bs[tx][kk],      w1 = Bs[tx + 16][kk];
                acc00 = fmaf(a0, w0, acc00);
                acc01 = fmaf(a0, w1, acc01);
                acc10 = fmaf(a1, w0, acc10);
                acc11 = fmaf(a1, w1, acc11);
            }
            __syncthreads();
        }
        float b00 = 0.f, b16 = 0.f;
        if (z == 0) { b00 = bias[h0 + tx]; b16 = bias[h0 + tx + 16]; }
        float* outp = g_att_h_part + (size_t)z * B_ * H_;
        outp[(size_t)(b0 + ty)      * H_ + h0 + tx]      = acc00 + b00;
        outp[(size_t)(b0 + ty)      * H_ + h0 + tx + 16] = acc01 + b16;
        outp[(size_t)(b0 + ty + 16) * H_ + h0 + tx]      = acc10 + b00;
        outp[(size_t)(b0 + ty + 16) * H_ + h0 + tx + 16] = acc11 + b16;
    }
}

// ---------------------------------------------------------------------------
// Phase 1: scores. 1024 items: (b, quarter of S). att_h reduced+cached in smem.
// ---------------------------------------------------------------------------
__device__ void phase_scores(char* smem,
                             const float* __restrict__ p_att,
                             const float* __restrict__ in_w,
                             const float* __restrict__ alpha_w,
                             const float* __restrict__ alpha_b) {
    float* sh_ah = (float*)smem;           // H_
    float* sh_al = sh_ah + H_;             // H_
    const int tid = threadIdx.x;
    const int warp = tid >> 5, lane = tid & 31;
    const int nitems = B_ * 4;

    for (int item = blockIdx.x; item < nitems; item += gridDim.x) {
        const int b = item >> 2;
        const int c = item & 3;

        for (int i = tid; i < H_; i += NTHREADS) {
            size_t o = (size_t)b * H_ + i;
            float v = g_att_h_part[o]
                    + g_att_h_part[(size_t)1 * B_ * H_ + o]
                    + g_att_h_part[(size_t)2 * B_ * H_ + o]
                    + g_att_h_part[(size_t)3 * B_ * H_ + o];
            sh_ah[i] = v;
            sh_al[i] = alpha_w[i];
        }
        __syncthreads();

        const float4* ah4 = (const float4*)sh_ah;
        const float4* al4 = (const float4*)sh_al;
        for (int sl = warp; sl < SCHUNK; sl += 8) {
            const int s = c * SCHUNK + sl;
            const float iw = in_w[b * S_ + s];
            const float4* p4 = (const float4*)(p_att + ((size_t)b * S_ + s) * H_);
            float acc = 0.f;
            #pragma unroll
            for (int j = 0; j < 4; j++) {
                float4 p = p4[j * 32 + lane];
                float4 a = ah4[j * 32 + lane];
                float4 w = al4[j * 32 + lane];
                acc += tanh_fast(fmaf(iw, p.x, a.x)) * w.x;
                acc += tanh_fast(fmaf(iw, p.y, a.y)) * w.y;
                acc += tanh_fast(fmaf(iw, p.z, a.z)) * w.z;
                acc += tanh_fast(fmaf(iw, p.w, a.w)) * w.w;
            }
            #pragma unroll
            for (int o = 16; o; o >>= 1)
                acc += __shfl_xor_sync(0xffffffffu, acc, o);
            if (lane == 0)
                g_scores[b * S_ + s] = acc + alpha_b[0];
        }
        __syncthreads();
    }
}

// ---------------------------------------------------------------------------
// Phase 2: inline softmax + partial pooling. 1024 items: (b, sc).
// Each block recomputes softmax for its b (deterministic, identical order).
// sc==0 items also write the weight output.
// ---------------------------------------------------------------------------
__device__ void phase_pool(char* smem,
                           const float* __restrict__ att_feats,
                           float* __restrict__ weight_out) {
    float* ws  = (float*)smem;            // S_ normalized weights
    float* red = ws + 200;                // 8 warp partials
    const int tid = threadIdx.x;
    const int warp = tid >> 5, lane = tid & 31;
    const int nitems = B_ * NSPOOL;

    for (int item = blockIdx.x; item < nitems; item += gridDim.x) {
        const int b  = item >> 2;
        const int sc = item & 3;

        // softmax over S_ (256 threads, one score each)
        float v = (tid < S_) ? g_scores[b * S_ + tid] : -1e30f;
        float m = v;
        #pragma unroll
        for (int o = 16; o; o >>= 1) m = fmaxf(m, __shfl_xor_sync(0xffffffffu, m, o));
        if (lane == 0) red[warp] = m;
        __syncthreads();
        if (tid == 0) {
            float mm = red[0];
            #pragma unroll
            for (int i = 1; i < 8; i++) mm = fmaxf(mm, red[i]);
            red[0] = mm;
        }
        __syncthreads();
        m = red[0];
        __syncthreads();

        float e = (tid < S_) ? __expf(v - m) : 0.f;
        float su = e;
        #pragma unroll
        for (int o = 16; o; o >>= 1) su += __shfl_xor_sync(0xffffffffu, su, o);
        if (lane == 0) red[warp] = su;
        __syncthreads();
        if (tid == 0) {
            float ss = 0.f;
            #pragma unroll
            for (int i = 0; i < 8; i++) ss += red[i];
            red[0] = ss;
        }
        __syncthreads();
        const float inv = 1.0f / red[0];
        const float wnorm = e * inv;
        if (tid < S_) {
            ws[tid] = wnorm;
            if (sc == 0) weight_out[b * S_ + tid] = wnorm;
        }
        __syncthreads();

        // pooling over this item's S-chunk; thread = one float4 column
        const float* wsl = ws + sc * SCHUNK;
        const float4* af = (const float4*)(att_feats
                            + ((size_t)b * S_ + sc * SCHUNK) * R_);
        float4 acc = make_float4(0.f, 0.f, 0.f, 0.f);
        #pragma unroll 7
        for (int s = 0; s < SCHUNK; s++) {
            float w = wsl[s];
            float4 vv = af[(size_t)s * (R_ / 4) + tid];
            acc.x = fmaf(w, vv.x, acc.x);
            acc.y = fmaf(w, vv.y, acc.y);
            acc.z = fmaf(w, vv.z, acc.z);
            acc.w = fmaf(w, vv.w, acc.w);
        }
        float4* part = (float4*)(g_pool_part + ((size_t)sc * B_ + b) * R_);
        part[tid] = acc;
        __syncthreads();
    }
}

// ---------------------------------------------------------------------------
// Phase 3: reduce 4 pool partials -> att_res. 256 items x 256 float4.
// ---------------------------------------------------------------------------
__device__ void phase_reduce(float* __restrict__ out) {
    const int tid = threadIdx.x;
    const int nitems = B_ * R_ / 4 / NTHREADS;   // 256
    const float4* p0 = (const float4*)g_pool_part;
    const float4* p1 = (const float4*)(g_pool_part + (size_t)1 * B_ * R_);
    const float4* p2 = (const float4*)(g_pool_part + (size_t)2 * B_ * R_);
    const float4* p3 = (const float4*)(g_pool_part + (size_t)3 * B_ * R_);

    for (int item = blockIdx.x; item < nitems; item += gridDim.x) {
        const int idx = item * NTHREADS + tid;
        float4 a = p0[idx], b = p1[idx], c = p2[idx], d = p3[idx];
        float4 r;
        r.x = (a.x + b.x) + (c.x + d.x);
        r.y = (a.y + b.y) + (c.y + d.y);
        r.z = (a.z + b.z) + (c.z + d.z);
        r.w = (a.w + b.w) + (c.w + d.w);
        ((float4*)out)[idx] = r;
    }
}

// ---------------------------------------------------------------------------
// The single persistent kernel.
// ---------------------------------------------------------------------------
__global__ void __launch_bounds__(NTHREADS, 8)
k_fused(const float* __restrict__ att_feats,
        const float* __restrict__ p_att,
        const float* __restrict__ hidden,
        const float* __restrict__ in_w,
        const float* __restrict__ h2w,
        const float* __restrict__ h2b,
        const float* __restrict__ aw,
        const float* __restrict__ ab,
        float* __restrict__ att_res,
        float* __restrict__ weight_out) {
    __shared__ __align__(16) char smem[2 * 32 * 33 * sizeof(float)];  // 8448 B

    phase_h2att(smem, hidden, h2w, h2b);
    grid_barrier();
    phase_scores(smem, p_att, in_w, aw, ab);
    grid_barrier();
    phase_pool(smem, att_feats, weight_out);
    grid_barrier();
    phase_reduce(att_res);
}

// ---------------------------------------------------------------------------
extern "C" void kernel_launch(void* const* d_in, const int* in_sizes, int n_in,
                              void* d_out, int out_size) {
    const float* att_feats = (const float*)d_in[0];  // [B,S,R]
    const float* p_att     = (const float*)d_in[1];  // [B,S,H]
    const float* hidden    = (const float*)d_in[2];  // [B,R]
    const float* in_w      = (const float*)d_in[3];  // [B,S]
    const float* h2w       = (const float*)d_in[4];  // [H,R]
    const float* h2b       = (const float*)d_in[5];  // [H]
    const float* aw        = (const float*)d_in[6];  // [1,H]
    const float* ab        = (const float*)d_in[7];  // [1]

    float* out     = (float*)d_out;
    float* att_res = out;                 // [B,R]
    float* weight  = out + B_ * R_;       // [B,S]

    // Size the grid to guaranteed co-residency (software grid barrier!).
    int dev = 0, sms = 148, maxb = 0;
    cudaGetDevice(&dev);
    cudaDeviceGetAttribute(&sms, cudaDevAttrMultiProcessorCount, dev);
    cudaOccupancyMaxActiveBlocksPerMultiprocessor(&maxb, k_fused, NTHREADS, 0);
    if (maxb < 1) maxb = 1;
    int grid = sms * maxb;

    k_fused<<<grid, NTHREADS>>>(att_feats, p_att, hidden, in_w,
                                h2w, h2b, aw, ab, att_res, weight);
}

// round 8
// speedup vs baseline: 1.2167x; 1.2167x over previous
#include <cuda_runtime.h>

#define B_ 256
#define S_ 196
#define R_ 1024
#define H_ 512

#define KSPLIT 4
#define KCHUNK (R_ / KSPLIT)
#define NSPOOL 8

// Scratch (no allocations allowed anywhere)
__device__ float g_att_h_part[KSPLIT * B_ * H_];
__device__ float g_scores[B_ * S_];
__device__ float g_pool_part[NSPOOL * B_ * R_];

__device__ __forceinline__ float tanh_fast(float x) {
    float y;
    asm("tanh.approx.f32 %0, %1;" : "=f"(y) : "f"(x));
    return y;
}

// ---------------------------------------------------------------------------
// Kernel A: partial att_h. grid (H/32, B/32, KSPLIT), 256 threads.
// ---------------------------------------------------------------------------
__global__ void k_h2att(const float* __restrict__ hidden,
                        const float* __restrict__ W,
                        const float* __restrict__ bias) {
    __shared__ float As[32][33];
    __shared__ float Bs[32][33];
    const int b0 = blockIdx.y * 32;
    const int h0 = blockIdx.x * 32;
    const int z  = blockIdx.z;
    const int tid = threadIdx.x;
    const int tx = tid & 15;
    const int ty = tid >> 4;
    float acc00 = 0.f, acc01 = 0.f, acc10 = 0.f, acc11 = 0.f;

    const int kbeg = z * KCHUNK;
    for (int k0 = kbeg; k0 < kbeg + KCHUNK; k0 += 32) {
        #pragma unroll
        for (int i = 0; i < 4; i++) {
            int idx = tid + i * 256;
            int r = idx >> 5, c = idx & 31;
            As[r][c] = hidden[(size_t)(b0 + r) * R_ + k0 + c];
            Bs[r][c] = W[(size_t)(h0 + r) * R_ + k0 + c];
        }
        __syncthreads();
        #pragma unroll
        for (int kk = 0; kk < 32; kk++) {
            float a0 = As[ty][kk],      a1 = As[ty + 16][kk];
            float w0 = Bs[tx][kk],      w1 = Bs[tx + 16][kk];
            acc00 = fmaf(a0, w0, acc00);
            acc01 = fmaf(a0, w1, acc01);
            acc10 = fmaf(a1, w0, acc10);
            acc11 = fmaf(a1, w1, acc11);
        }
        __syncthreads();
    }
    float b00 = 0.f, b16 = 0.f;
    if (z == 0) { b00 = bias[h0 + tx]; b16 = bias[h0 + tx + 16]; }
    float* outp = g_att_h_part + (size_t)z * B_ * H_;
    outp[(size_t)(b0 + ty)      * H_ + h0 + tx]      = acc00 + b00;
    outp[(size_t)(b0 + ty)      * H_ + h0 + tx + 16] = acc01 + b16;
    outp[(size_t)(b0 + ty + 16) * H_ + h0 + tx]      = acc10 + b00;
    outp[(size_t)(b0 + ty + 16) * H_ + h0 + tx + 16] = acc11 + b16;
}

// ---------------------------------------------------------------------------
// Kernel B: scores. grid (2, B), 512 threads (16 warps).
// Each block: one b, half of S (98 rows). att_h partials reduced once into smem.
// ---------------------------------------------------------------------------
__global__ void __launch_bounds__(512)
k_scores(const float* __restrict__ p_att,
         const float* __restrict__ in_w,
         const float* __restrict__ alpha_w,
         const float* __restrict__ alpha_b) {
    __shared__ __align__(16) float sh_ah[H_];
    __shared__ __align__(16) float sh_al[H_];
    const int b = blockIdx.y;
    const int c = blockIdx.x;          // 0 or 1 (half of S)
    const int tid = threadIdx.x;

    if (tid < H_) {
        size_t o = (size_t)b * H_ + tid;
        float v = g_att_h_part[o]
                + g_att_h_part[(size_t)1 * B_ * H_ + o]
                + g_att_h_part[(size_t)2 * B_ * H_ + o]
                + g_att_h_part[(size_t)3 * B_ * H_ + o];
        sh_ah[tid] = v;
        sh_al[tid] = alpha_w[tid];
    }
    __syncthreads();

    const int warp = tid >> 5, lane = tid & 31;
    const float4* ah4 = (const float4*)sh_ah;
    const float4* al4 = (const float4*)sh_al;
    const float ab0 = alpha_b[0];

    for (int sl = warp; sl < S_ / 2; sl += 16) {
        const int s = c * (S_ / 2) + sl;
        const float iw = in_w[b * S_ + s];
        const float4* p4 = (const float4*)(p_att + ((size_t)b * S_ + s) * H_);
        float acc = 0.f;
        #pragma unroll
        for (int j = 0; j < 4; j++) {
            float4 p = p4[j * 32 + lane];
            float4 a = ah4[j * 32 + lane];
            float4 w = al4[j * 32 + lane];
            acc += tanh_fast(fmaf(iw, p.x, a.x)) * w.x;
            acc += tanh_fast(fmaf(iw, p.y, a.y)) * w.y;
            acc += tanh_fast(fmaf(iw, p.z, a.z)) * w.z;
            acc += tanh_fast(fmaf(iw, p.w, a.w)) * w.w;
        }
        #pragma unroll
        for (int o = 16; o; o >>= 1)
            acc += __shfl_xor_sync(0xffffffffu, acc, o);
        if (lane == 0)
            g_scores[b * S_ + s] = acc + ab0;
    }
}

// ---------------------------------------------------------------------------
// Kernel C: fused softmax + partial pooling. grid (NSPOOL, B), 256 threads.
// Every block recomputes the (deterministic) softmax for its b from g_scores;
// the sc==0 block also writes the weight output. Then pools its s-chunk.
// ---------------------------------------------------------------------------
__global__ void __launch_bounds__(256)
k_pool(const float* __restrict__ att_feats,
       float* __restrict__ weight_out) {
    __shared__ float ws[S_];
    __shared__ float red[8];
    const int b  = blockIdx.y;
    const int sc = blockIdx.x;
    const int tid = threadIdx.x;
    const int warp = tid >> 5, lane = tid & 31;

    // --- softmax over S (256 threads, one score each) ---
    float v = (tid < S_) ? g_scores[b * S_ + tid] : -1e30f;
    float m = v;
    #pragma unroll
    for (int o = 16; o; o >>= 1) m = fmaxf(m, __shfl_xor_sync(0xffffffffu, m, o));
    if (lane == 0) red[warp] = m;
    __syncthreads();
    if (tid == 0) {
        float mm = red[0];
        #pragma unroll
        for (int i = 1; i < 8; i++) mm = fmaxf(mm, red[i]);
        red[0] = mm;
    }
    __syncthreads();
    m = red[0];
    __syncthreads();

    float e = (tid < S_) ? __expf(v - m) : 0.f;
    float su = e;
    #pragma unroll
    for (int o = 16; o; o >>= 1) su += __shfl_xor_sync(0xffffffffu, su, o);
    if (lane == 0) red[warp] = su;
    __syncthreads();
    if (tid == 0) {
        float ss = 0.f;
        #pragma unroll
        for (int i = 0; i < 8; i++) ss += red[i];
        red[0] = ss;
    }
    __syncthreads();
    const float inv = 1.0f / red[0];
    if (tid < S_) {
        float wnorm = e * inv;
        ws[tid] = wnorm;
        if (sc == 0) weight_out[b * S_ + tid] = wnorm;
    }
    __syncthreads();

    // --- partial pooling over this block's s-chunk (uneven 24/25 split) ---
    const int s0 = (sc * S_) / NSPOOL;
    const int s1 = ((sc + 1) * S_) / NSPOOL;
    const float4* af = (const float4*)(att_feats + ((size_t)b * S_ + s0) * R_);
    float4 acc = make_float4(0.f, 0.f, 0.f, 0.f);

    #pragma unroll 4
    for (int s = 0; s < s1 - s0; s++) {
        float w = ws[s0 + s];
        float4 vv = af[(size_t)s * (R_ / 4) + tid];
        acc.x = fmaf(w, vv.x, acc.x);
        acc.y = fmaf(w, vv.y, acc.y);
        acc.z = fmaf(w, vv.z, acc.z);
        acc.w = fmaf(w, vv.w, acc.w);
    }
    float4* part = (float4*)(g_pool_part + ((size_t)sc * B_ + b) * R_);
    part[tid] = acc;
}

// ---------------------------------------------------------------------------
// Kernel D: reduce NSPOOL partials -> att_res. 65536 float4 outputs.
// ---------------------------------------------------------------------------
__global__ void k_pool_reduce(float* __restrict__ out) {
    const int idx = blockIdx.x * 256 + threadIdx.x;   // float4 index over B*R/4
    float4 r = make_float4(0.f, 0.f, 0.f, 0.f);
    #pragma unroll
    for (int p = 0; p < NSPOOL; p++) {
        const float4* pp = (const float4*)(g_pool_part + (size_t)p * B_ * R_);
        float4 a = pp[idx];
        r.x += a.x; r.y += a.y; r.z += a.z; r.w += a.w;
    }
    ((float4*)out)[idx] = r;
}

// ---------------------------------------------------------------------------
extern "C" void kernel_launch(void* const* d_in, const int* in_sizes, int n_in,
                              void* d_out, int out_size) {
    const float* att_feats = (const float*)d_in[0];  // [B,S,R]
    const float* p_att     = (const float*)d_in[1];  // [B,S,H]
    const float* hidden    = (const float*)d_in[2];  // [B,R]
    const float* in_w      = (const float*)d_in[3];  // [B,S]
    const float* h2w       = (const float*)d_in[4];  // [H,R]
    const float* h2b       = (const float*)d_in[5];  // [H]
    const float* aw        = (const float*)d_in[6];  // [1,H]
    const float* ab        = (const float*)d_in[7];  // [1]

    float* out     = (float*)d_out;
    float* att_res = out;                 // [B,R]
    float* weight  = out + B_ * R_;       // [B,S]

    k_h2att      <<<dim3(H_ / 32, B_ / 32, KSPLIT), 256>>>(hidden, h2w, h2b);
    k_scores     <<<dim3(2, B_), 512>>>(p_att, in_w, aw, ab);
    k_pool       <<<dim3(NSPOOL, B_), 256>>>(att_feats, weight);
    k_pool_reduce<<<B_ * R_ / 4 / 256, 256>>>(att_res);
}

// round 11
// speedup vs baseline: 1.2474x; 1.0252x over previous
#include <cuda_runtime.h>

#define B_ 256
#define S_ 196
#define R_ 1024
#define H_ 512

#define KSPLIT 4
#define KCHUNK (R_ / KSPLIT)

// Scratch (no allocations allowed anywhere)
__device__ float g_att_h_part[KSPLIT * B_ * H_];
__device__ float g_scores[B_ * S_];

__device__ __forceinline__ float tanh_fast(float x) {
    float y;
    asm("tanh.approx.f32 %0, %1;" : "=f"(y) : "f"(x));
    return y;
}

// ---------------------------------------------------------------------------
// Kernel A: partial att_h. grid (H/32, B/32, KSPLIT), 256 threads.
// ---------------------------------------------------------------------------
__global__ void k_h2att(const float* __restrict__ hidden,
                        const float* __restrict__ W,
                        const float* __restrict__ bias) {
    __shared__ float As[32][33];
    __shared__ float Bs[32][33];
    const int b0 = blockIdx.y * 32;
    const int h0 = blockIdx.x * 32;
    const int z  = blockIdx.z;
    const int tid = threadIdx.x;
    const int tx = tid & 15;
    const int ty = tid >> 4;
    float acc00 = 0.f, acc01 = 0.f, acc10 = 0.f, acc11 = 0.f;

    const int kbeg = z * KCHUNK;
    for (int k0 = kbeg; k0 < kbeg + KCHUNK; k0 += 32) {
        #pragma unroll
        for (int i = 0; i < 4; i++) {
            int idx = tid + i * 256;
            int r = idx >> 5, c = idx & 31;
            As[r][c] = hidden[(size_t)(b0 + r) * R_ + k0 + c];
            Bs[r][c] = W[(size_t)(h0 + r) * R_ + k0 + c];
        }
        __syncthreads();
        #pragma unroll
        for (int kk = 0; kk < 32; kk++) {
            float a0 = As[ty][kk],      a1 = As[ty + 16][kk];
            float w0 = Bs[tx][kk],      w1 = Bs[tx + 16][kk];
            acc00 = fmaf(a0, w0, acc00);
            acc01 = fmaf(a0, w1, acc01);
            acc10 = fmaf(a1, w0, acc10);
            acc11 = fmaf(a1, w1, acc11);
        }
        __syncthreads();
    }
    float b00 = 0.f, b16 = 0.f;
    if (z == 0) { b00 = bias[h0 + tx]; b16 = bias[h0 + tx + 16]; }
    float* outp = g_att_h_part + (size_t)z * B_ * H_;
    outp[(size_t)(b0 + ty)      * H_ + h0 + tx]      = acc00 + b00;
    outp[(size_t)(b0 + ty)      * H_ + h0 + tx + 16] = acc01 + b16;
    outp[(size_t)(b0 + ty + 16) * H_ + h0 + tx]      = acc10 + b00;
    outp[(size_t)(b0 + ty + 16) * H_ + h0 + tx + 16] = acc11 + b16;
}

// ---------------------------------------------------------------------------
// Kernel B: scores. grid (2, B), 512 threads (16 warps).
// Each block: one b, half of S (98 rows). att_h partials reduced once into smem.
// ---------------------------------------------------------------------------
__global__ void __launch_bounds__(512)
k_scores(const float* __restrict__ p_att,
         const float* __restrict__ in_w,
         const float* __restrict__ alpha_w,
         const float* __restrict__ alpha_b) {
    __shared__ __align__(16) float sh_ah[H_];
    __shared__ __align__(16) float sh_al[H_];
    const int b = blockIdx.y;
    const int c = blockIdx.x;          // 0 or 1 (half of S)
    const int tid = threadIdx.x;

    if (tid < H_) {
        size_t o = (size_t)b * H_ + tid;
        float v = g_att_h_part[o]
                + g_att_h_part[(size_t)1 * B_ * H_ + o]
                + g_att_h_part[(size_t)2 * B_ * H_ + o]
                + g_att_h_part[(size_t)3 * B_ * H_ + o];
        sh_ah[tid] = v;
        sh_al[tid] = alpha_w[tid];
    }
    __syncthreads();

    const int warp = tid >> 5, lane = tid & 31;
    const float4* ah4 = (const float4*)sh_ah;
    const float4* al4 = (const float4*)sh_al;
    const float ab0 = alpha_b[0];

    for (int sl = warp; sl < S_ / 2; sl += 16) {
        const int s = c * (S_ / 2) + sl;
        const float iw = in_w[b * S_ + s];
        const float4* p4 = (const float4*)(p_att + ((size_t)b * S_ + s) * H_);
        float acc = 0.f;
        #pragma unroll
        for (int j = 0; j < 4; j++) {
            float4 p = p4[j * 32 + lane];
            float4 a = ah4[j * 32 + lane];
            float4 w = al4[j * 32 + lane];
            acc += tanh_fast(fmaf(iw, p.x, a.x)) * w.x;
            acc += tanh_fast(fmaf(iw, p.y, a.y)) * w.y;
            acc += tanh_fast(fmaf(iw, p.z, a.z)) * w.z;
            acc += tanh_fast(fmaf(iw, p.w, a.w)) * w.w;
        }
        #pragma unroll
        for (int o = 16; o; o >>= 1)
            acc += __shfl_xor_sync(0xffffffffu, acc, o);
        if (lane == 0)
            g_scores[b * S_ + s] = acc + ab0;
    }
}

// ---------------------------------------------------------------------------
// Kernel C: fused softmax + DIRECT pooling. grid (4, B), 256 threads.
// Each block recomputes the (deterministic) softmax for its b from g_scores;
// the rc==0 block also writes the weight output. Then each thread owns ONE
// r column (scalar) and accumulates over all 196 s — no partials, no reduce.
// ---------------------------------------------------------------------------
__global__ void __launch_bounds__(256)
k_pool(const float* __restrict__ att_feats,
       float* __restrict__ weight_out,
       float* __restrict__ att_res) {
    __shared__ float ws[S_];
    __shared__ float red[8];
    const int b  = blockIdx.y;
    const int rc = blockIdx.x;         // r chunk 0..3
    const int tid = threadIdx.x;
    const int warp = tid >> 5, lane = tid & 31;

    // --- softmax over S (256 threads, one score each) ---
    float v = (tid < S_) ? g_scores[b * S_ + tid] : -1e30f;
    float m = v;
    #pragma unroll
    for (int o = 16; o; o >>= 1) m = fmaxf(m, __shfl_xor_sync(0xffffffffu, m, o));
    if (lane == 0) red[warp] = m;
    __syncthreads();
    if (tid == 0) {
        float mm = red[0];
        #pragma unroll
        for (int i = 1; i < 8; i++) mm = fmaxf(mm, red[i]);
        red[0] = mm;
    }
    __syncthreads();
    m = red[0];
    __syncthreads();

    float e = (tid < S_) ? __expf(v - m) : 0.f;
    float su = e;
    #pragma unroll
    for (int o = 16; o; o >>= 1) su += __shfl_xor_sync(0xffffffffu, su, o);
    if (lane == 0) red[warp] = su;
    __syncthreads();
    if (tid == 0) {
        float ss = 0.f;
        #pragma unroll
        for (int i = 0; i < 8; i++) ss += red[i];
        red[0] = ss;
    }
    __syncthreads();
    const float inv = 1.0f / red[0];
    if (tid < S_) {
        float wnorm = e * inv;
        ws[tid] = wnorm;
        if (rc == 0) weight_out[b * S_ + tid] = wnorm;
    }
    __syncthreads();

    // --- direct pooling: this thread's r column, all 196 s ---
    const int r = rc * 256 + tid;
    const float* af = att_feats + (size_t)b * S_ * R_ + r;
    float acc = 0.f;
    #pragma unroll 7
    for (int s = 0; s < S_; s++) {
        acc = fmaf(ws[s], af[(size_t)s * R_], acc);
    }
    att_res[(size_t)b * R_ + r] = acc;
}

// ---------------------------------------------------------------------------
extern "C" void kernel_launch(void* const* d_in, const int* in_sizes, int n_in,
                              void* d_out, int out_size) {
    const float* att_feats = (const float*)d_in[0];  // [B,S,R]
    const float* p_att     = (const float*)d_in[1];  // [B,S,H]
    const float* hidden    = (const float*)d_in[2];  // [B,R]
    const float* in_w      = (const float*)d_in[3];  // [B,S]
    const float* h2w       = (const float*)d_in[4];  // [H,R]
    const float* h2b       = (const float*)d_in[5];  // [H]
    const float* aw        = (const float*)d_in[6];  // [1,H]
    const float* ab        = (const float*)d_in[7];  // [1]

    float* out     = (float*)d_out;
    float* att_res = out;                 // [B,R]
    float* weight  = out + B_ * R_;       // [B,S]

    k_h2att <<<dim3(H_ / 32, B_ / 32, KSPLIT), 256>>>(hidden, h2w, h2b);
    k_scores<<<dim3(2, B_), 512>>>(p_att, in_w, aw, ab);
    k_pool  <<<dim3(4, B_), 256>>>(att_feats, weight, att_res);
}

// round 12
// speedup vs baseline: 1.3372x; 1.0720x over previous
#include <cuda_runtime.h>

#define B_ 256
#define S_ 196
#define R_ 1024
#define H_ 512

#define KSPLIT 4
#define KCHUNK (R_ / KSPLIT)

// GEMM tiling for k_h2att
#define BM 64
#define BN 64
#define BK 16

// Scratch (no allocations allowed anywhere)
__device__ float g_att_h_part[KSPLIT * B_ * H_];
__device__ float g_scores[B_ * S_];

__device__ __forceinline__ float tanh_fast(float x) {
    float y;
    asm("tanh.approx.f32 %0, %1;" : "=f"(y) : "f"(x));
    return y;
}

// ---------------------------------------------------------------------------
// Kernel A: partial att_h = hidden @ W^T (+bias on z==0 split).
// grid (H/BN=8, B/BM=4, KSPLIT=4), 256 threads, 4x4 micro-tile,
// k-major smem (transposed) so the inner loop is 2x LDS.128 + 16 FMA.
// ---------------------------------------------------------------------------
__global__ void __launch_bounds__(256)
k_h2att(const float* __restrict__ hidden,
        const float* __restrict__ W,
        const float* __restrict__ bias) {
    __shared__ __align__(16) float As[BK][BM + 4];   // [kk][b-row]
    __shared__ __align__(16) float Bs[BK][BN + 4];   // [kk][h-col]
    const int h0 = blockIdx.x * BN;
    const int b0 = blockIdx.y * BM;
    const int z  = blockIdx.z;
    const int tid = threadIdx.x;

    const int lrow = tid >> 2;            // 0..63 (row to stage)
    const int lk   = (tid & 3) * 4;       // 0,4,8,12 (k quad)

    const int tx4 = (tid & 15) * 4;       // h micro col
    const int ty4 = (tid >> 4) * 4;       // b micro row

    float acc[4][4] = {};

    const int kbeg = z * KCHUNK;
    for (int k0 = kbeg; k0 < kbeg + KCHUNK; k0 += BK) {
        float4 av = *(const float4*)&hidden[(size_t)(b0 + lrow) * R_ + k0 + lk];
        float4 bv = *(const float4*)&W[(size_t)(h0 + lrow) * R_ + k0 + lk];
        As[lk + 0][lrow] = av.x;
        As[lk + 1][lrow] = av.y;
        As[lk + 2][lrow] = av.z;
        As[lk + 3][lrow] = av.w;
        Bs[lk + 0][lrow] = bv.x;
        Bs[lk + 1][lrow] = bv.y;
        Bs[lk + 2][lrow] = bv.z;
        Bs[lk + 3][lrow] = bv.w;
        __syncthreads();

        #pragma unroll
        for (int kk = 0; kk < BK; kk++) {
            float4 a = *(const float4*)&As[kk][ty4];
            float4 b = *(const float4*)&Bs[kk][tx4];
            acc[0][0] = fmaf(a.x, b.x, acc[0][0]);
            acc[0][1] = fmaf(a.x, b.y, acc[0][1]);
            acc[0][2] = fmaf(a.x, b.z, acc[0][2]);
            acc[0][3] = fmaf(a.x, b.w, acc[0][3]);
            acc[1][0] = fmaf(a.y, b.x, acc[1][0]);
            acc[1][1] = fmaf(a.y, b.y, acc[1][1]);
            acc[1][2] = fmaf(a.y, b.z, acc[1][2]);
            acc[1][3] = fmaf(a.y, b.w, acc[1][3]);
            acc[2][0] = fmaf(a.z, b.x, acc[2][0]);
            acc[2][1] = fmaf(a.z, b.y, acc[2][1]);
            acc[2][2] = fmaf(a.z, b.z, acc[2][2]);
            acc[2][3] = fmaf(a.z, b.w, acc[2][3]);
            acc[3][0] = fmaf(a.w, b.x, acc[3][0]);
            acc[3][1] = fmaf(a.w, b.y, acc[3][1]);
            acc[3][2] = fmaf(a.w, b.z, acc[3][2]);
            acc[3][3] = fmaf(a.w, b.w, acc[3][3]);
        }
        __syncthreads();
    }

    float4 bias4 = make_float4(0.f, 0.f, 0.f, 0.f);
    if (z == 0) bias4 = *(const float4*)&bias[h0 + tx4];

    float* outp = g_att_h_part + (size_t)z * B_ * H_;
    #pragma unroll
    for (int i = 0; i < 4; i++) {
        float4 r = make_float4(acc[i][0] + bias4.x,
                               acc[i][1] + bias4.y,
                               acc[i][2] + bias4.z,
                               acc[i][3] + bias4.w);
        *(float4*)&outp[(size_t)(b0 + ty4 + i) * H_ + h0 + tx4] = r;
    }
}

// ---------------------------------------------------------------------------
// Kernel B: scores. grid (2, B), 512 threads (16 warps).
// Each block: one b, half of S (98 rows). att_h partials reduced once into smem.
// ---------------------------------------------------------------------------
__global__ void __launch_bounds__(512)
k_scores(const float* __restrict__ p_att,
         const float* __restrict__ in_w,
         const float* __restrict__ alpha_w,
         const float* __restrict__ alpha_b) {
    __shared__ __align__(16) float sh_ah[H_];
    __shared__ __align__(16) float sh_al[H_];
    const int b = blockIdx.y;
    const int c = blockIdx.x;          // 0 or 1 (half of S)
    const int tid = threadIdx.x;

    if (tid < H_) {
        size_t o = (size_t)b * H_ + tid;
        float v = g_att_h_part[o]
                + g_att_h_part[(size_t)1 * B_ * H_ + o]
                + g_att_h_part[(size_t)2 * B_ * H_ + o]
                + g_att_h_part[(size_t)3 * B_ * H_ + o];
        sh_ah[tid] = v;
        sh_al[tid] = alpha_w[tid];
    }
    __syncthreads();

    const int warp = tid >> 5, lane = tid & 31;
    const float4* ah4 = (const float4*)sh_ah;
    const float4* al4 = (const float4*)sh_al;
    const float ab0 = alpha_b[0];

    for (int sl = warp; sl < S_ / 2; sl += 16) {
        const int s = c * (S_ / 2) + sl;
        const float iw = in_w[b * S_ + s];
        const float4* p4 = (const float4*)(p_att + ((size_t)b * S_ + s) * H_);
        float acc = 0.f;
        #pragma unroll
        for (int j = 0; j < 4; j++) {
            float4 p = p4[j * 32 + lane];
            float4 a = ah4[j * 32 + lane];
            float4 w = al4[j * 32 + lane];
            acc += tanh_fast(fmaf(iw, p.x, a.x)) * w.x;
            acc += tanh_fast(fmaf(iw, p.y, a.y)) * w.y;
            acc += tanh_fast(fmaf(iw, p.z, a.z)) * w.z;
            acc += tanh_fast(fmaf(iw, p.w, a.w)) * w.w;
        }
        #pragma unroll
        for (int o = 16; o; o >>= 1)
            acc += __shfl_xor_sync(0xffffffffu, acc, o);
        if (lane == 0)
            g_scores[b * S_ + s] = acc + ab0;
    }
}

// ---------------------------------------------------------------------------
// Kernel C: fused softmax + DIRECT pooling. grid (4, B), 256 threads.
// Each block recomputes the (deterministic) softmax for its b from g_scores;
// the rc==0 block also writes the weight output. Then each thread owns ONE
// r column (scalar) and accumulates over all 196 s — no partials, no reduce.
// ---------------------------------------------------------------------------
__global__ void __launch_bounds__(256)
k_pool(const float* __restrict__ att_feats,
       float* __restrict__ weight_out,
       float* __restrict__ att_res) {
    __shared__ float ws[S_];
    __shared__ float red[8];
    const int b  = blockIdx.y;
    const int rc = blockIdx.x;         // r chunk 0..3
    const int tid = threadIdx.x;
    const int warp = tid >> 5, lane = tid & 31;

    // --- softmax over S (256 threads, one score each) ---
    float v = (tid < S_) ? g_scores[b * S_ + tid] : -1e30f;
    float m = v;
    #pragma unroll
    for (int o = 16; o; o >>= 1) m = fmaxf(m, __shfl_xor_sync(0xffffffffu, m, o));
    if (lane == 0) red[warp] = m;
    __syncthreads();
    if (tid == 0) {
        float mm = red[0];
        #pragma unroll
        for (int i = 1; i < 8; i++) mm = fmaxf(mm, red[i]);
        red[0] = mm;
    }
    __syncthreads();
    m = red[0];
    __syncthreads();

    float e = (tid < S_) ? __expf(v - m) : 0.f;
    float su = e;
    #pragma unroll
    for (int o = 16; o; o >>= 1) su += __shfl_xor_sync(0xffffffffu, su, o);
    if (lane == 0) red[warp] = su;
    __syncthreads();
    if (tid == 0) {
        float ss = 0.f;
        #pragma unroll
        for (int i = 0; i < 8; i++) ss += red[i];
        red[0] = ss;
    }
    __syncthreads();
    const float inv = 1.0f / red[0];
    if (tid < S_) {
        float wnorm = e * inv;
        ws[tid] = wnorm;
        if (rc == 0) weight_out[b * S_ + tid] = wnorm;
    }
    __syncthreads();

    // --- direct pooling: this thread's r column, all 196 s ---
    const int r = rc * 256 + tid;
    const float* af = att_feats + (size_t)b * S_ * R_ + r;
    float acc = 0.f;
    #pragma unroll 7
    for (int s = 0; s < S_; s++) {
        acc = fmaf(ws[s], af[(size_t)s * R_], acc);
    }
    att_res[(size_t)b * R_ + r] = acc;
}

// ---------------------------------------------------------------------------
extern "C" void kernel_launch(void* const* d_in, const int* in_sizes, int n_in,
                              void* d_out, int out_size) {
    const float* att_feats = (const float*)d_in[0];  // [B,S,R]
    const float* p_att     = (const float*)d_in[1];  // [B,S,H]
    const float* hidden    = (const float*)d_in[2];  // [B,R]
    const float* in_w      = (const float*)d_in[3];  // [B,S]
    const float* h2w       = (const float*)d_in[4];  // [H,R]
    const float* h2b       = (const float*)d_in[5];  // [H]
    const float* aw        = (const float*)d_in[6];  // [1,H]
    const float* ab        = (const float*)d_in[7];  // [1]

    float* out     = (float*)d_out;
    float* att_res = out;                 // [B,R]
    float* weight  = out + B_ * R_;       // [B,S]

    k_h2att <<<dim3(H_ / BN, B_ / BM, KSPLIT), 256>>>(hidden, h2w, h2b);
    k_scores<<<dim3(2, B_), 512>>>(p_att, in_w, aw, ab);
    k_pool  <<<dim3(4, B_), 256>>>(att_feats, weight, att_res);
}

// round 13
// speedup vs baseline: 1.4384x; 1.0757x over previous
#include <cuda_runtime.h>

#define B_ 256
#define S_ 196
#define R_ 1024
#define H_ 512

#define KSPLIT 8
#define KCHUNK (R_ / KSPLIT)     // 128

// GEMM tiling for k_h2att
#define BM 64
#define BN 64
#define BK 16
#define NTILES (KCHUNK / BK)     // 8

// Scratch (no allocations allowed anywhere)
__device__ float g_att_h_part[KSPLIT * B_ * H_];
__device__ float g_scores[B_ * S_];

__device__ __forceinline__ float tanh_fast(float x) {
    float y;
    asm("tanh.approx.f32 %0, %1;" : "=f"(y) : "f"(x));
    return y;
}

// ---------------------------------------------------------------------------
// Kernel A: partial att_h = hidden @ W^T (+bias on z==0 split).
// grid (H/BN=8, B/BM=4, KSPLIT=8) = 256 blocks, 256 threads, 4x4 micro-tile.
// Ping-pong smem buffers + register staging: next tile's LDGs issue before
// the current tile's math, hiding global latency. One sync per k-tile.
// ---------------------------------------------------------------------------
__global__ void __launch_bounds__(256)
k_h2att(const float* __restrict__ hidden,
        const float* __restrict__ W,
        const float* __restrict__ bias) {
    __shared__ __align__(16) float As[2][BK][BM + 4];   // [buf][kk][b-row]
    __shared__ __align__(16) float Bs[2][BK][BN + 4];   // [buf][kk][h-col]
    const int h0 = blockIdx.x * BN;
    const int b0 = blockIdx.y * BM;
    const int z  = blockIdx.z;
    const int tid = threadIdx.x;

    const int lrow = tid >> 2;            // 0..63 (row to stage)
    const int lk   = (tid & 3) * 4;       // 0,4,8,12 (k quad)

    const int tx4 = (tid & 15) * 4;       // h micro col
    const int ty4 = (tid >> 4) * 4;       // b micro row

    float acc[4][4] = {};

    const int kbeg = z * KCHUNK;
    const float* ha = &hidden[(size_t)(b0 + lrow) * R_ + kbeg + lk];
    const float* wa = &W[(size_t)(h0 + lrow) * R_ + kbeg + lk];

    // prologue: stage tile 0 into buffer 0
    {
        float4 av = *(const float4*)ha;
        float4 bv = *(const float4*)wa;
        As[0][lk + 0][lrow] = av.x;
        As[0][lk + 1][lrow] = av.y;
        As[0][lk + 2][lrow] = av.z;
        As[0][lk + 3][lrow] = av.w;
        Bs[0][lk + 0][lrow] = bv.x;
        Bs[0][lk + 1][lrow] = bv.y;
        Bs[0][lk + 2][lrow] = bv.z;
        Bs[0][lk + 3][lrow] = bv.w;
    }
    __syncthreads();

    #pragma unroll
    for (int i = 0; i < NTILES; i++) {
        float4 av, bv;
        if (i + 1 < NTILES) {              // issue next tile's loads early
            av = *(const float4*)(ha + (i + 1) * BK);
            bv = *(const float4*)(wa + (i + 1) * BK);
        }

        const int p = i & 1;
        #pragma unroll
        for (int kk = 0; kk < BK; kk++) {
            float4 a = *(const float4*)&As[p][kk][ty4];
            float4 b = *(const float4*)&Bs[p][kk][tx4];
            acc[0][0] = fmaf(a.x, b.x, acc[0][0]);
            acc[0][1] = fmaf(a.x, b.y, acc[0][1]);
            acc[0][2] = fmaf(a.x, b.z, acc[0][2]);
            acc[0][3] = fmaf(a.x, b.w, acc[0][3]);
            acc[1][0] = fmaf(a.y, b.x, acc[1][0]);
            acc[1][1] = fmaf(a.y, b.y, acc[1][1]);
            acc[1][2] = fmaf(a.y, b.z, acc[1][2]);
            acc[1][3] = fmaf(a.y, b.w, acc[1][3]);
            acc[2][0] = fmaf(a.z, b.x, acc[2][0]);
            acc[2][1] = fmaf(a.z, b.y, acc[2][1]);
            acc[2][2] = fmaf(a.z, b.z, acc[2][2]);
            acc[2][3] = fmaf(a.z, b.w, acc[2][3]);
            acc[3][0] = fmaf(a.w, b.x, acc[3][0]);
            acc[3][1] = fmaf(a.w, b.y, acc[3][1]);
            acc[3][2] = fmaf(a.w, b.z, acc[3][2]);
            acc[3][3] = fmaf(a.w, b.w, acc[3][3]);
        }

        if (i + 1 < NTILES) {
            const int q = (i + 1) & 1;
            As[q][lk + 0][lrow] = av.x;
            As[q][lk + 1][lrow] = av.y;
            As[q][lk + 2][lrow] = av.z;
            As[q][lk + 3][lrow] = av.w;
            Bs[q][lk + 0][lrow] = bv.x;
            Bs[q][lk + 1][lrow] = bv.y;
            Bs[q][lk + 2][lrow] = bv.z;
            Bs[q][lk + 3][lrow] = bv.w;
            __syncthreads();
        }
    }

    float4 bias4 = make_float4(0.f, 0.f, 0.f, 0.f);
    if (z == 0) bias4 = *(const float4*)&bias[h0 + tx4];

    float* outp = g_att_h_part + (size_t)z * B_ * H_;
    #pragma unroll
    for (int i = 0; i < 4; i++) {
        float4 r = make_float4(acc[i][0] + bias4.x,
                               acc[i][1] + bias4.y,
                               acc[i][2] + bias4.z,
                               acc[i][3] + bias4.w);
        *(float4*)&outp[(size_t)(b0 + ty4 + i) * H_ + h0 + tx4] = r;
    }
}

// ---------------------------------------------------------------------------
// Kernel B: scores. grid (2, B), 512 threads (16 warps).
// Each block: one b, half of S (98 rows). att_h partials reduced once into smem.
// ---------------------------------------------------------------------------
__global__ void __launch_bounds__(512)
k_scores(const float* __restrict__ p_att,
         const float* __restrict__ in_w,
         const float* __restrict__ alpha_w,
         const float* __restrict__ alpha_b) {
    __shared__ __align__(16) float sh_ah[H_];
    __shared__ __align__(16) float sh_al[H_];
    const int b = blockIdx.y;
    const int c = blockIdx.x;          // 0 or 1 (half of S)
    const int tid = threadIdx.x;

    if (tid < H_) {
        size_t o = (size_t)b * H_ + tid;
        float v = 0.f;
        #pragma unroll
        for (int p = 0; p < KSPLIT; p++)
            v += g_att_h_part[(size_t)p * B_ * H_ + o];
        sh_ah[tid] = v;
        sh_al[tid] = alpha_w[tid];
    }
    __syncthreads();

    const int warp = tid >> 5, lane = tid & 31;
    const float4* ah4 = (const float4*)sh_ah;
    const float4* al4 = (const float4*)sh_al;
    const float ab0 = alpha_b[0];

    for (int sl = warp; sl < S_ / 2; sl += 16) {
        const int s = c * (S_ / 2) + sl;
        const float iw = in_w[b * S_ + s];
        const float4* p4 = (const float4*)(p_att + ((size_t)b * S_ + s) * H_);
        float acc = 0.f;
        #pragma unroll
        for (int j = 0; j < 4; j++) {
            float4 p = p4[j * 32 + lane];
            float4 a = ah4[j * 32 + lane];
            float4 w = al4[j * 32 + lane];
            acc += tanh_fast(fmaf(iw, p.x, a.x)) * w.x;
            acc += tanh_fast(fmaf(iw, p.y, a.y)) * w.y;
            acc += tanh_fast(fmaf(iw, p.z, a.z)) * w.z;
            acc += tanh_fast(fmaf(iw, p.w, a.w)) * w.w;
        }
        #pragma unroll
        for (int o = 16; o; o >>= 1)
            acc += __shfl_xor_sync(0xffffffffu, acc, o);
        if (lane == 0)
            g_scores[b * S_ + s] = acc + ab0;
    }
}

// ---------------------------------------------------------------------------
// Kernel C: fused softmax + DIRECT pooling. grid (4, B), 256 threads.
// Each block recomputes the (deterministic) softmax for its b from g_scores;
// the rc==0 block also writes the weight output. Then each thread owns ONE
// r column (scalar) and accumulates over all 196 s — no partials, no reduce.
// ---------------------------------------------------------------------------
__global__ void __launch_bounds__(256)
k_pool(const float* __restrict__ att_feats,
       float* __restrict__ weight_out,
       float* __restrict__ att_res) {
    __shared__ float ws[S_];
    __shared__ float red[8];
    const int b  = blockIdx.y;
    const int rc = blockIdx.x;         // r chunk 0..3
    const int tid = threadIdx.x;
    const int warp = tid >> 5, lane = tid & 31;

    // --- softmax over S (256 threads, one score each) ---
    float v = (tid < S_) ? g_scores[b * S_ + tid] : -1e30f;
    float m = v;
    #pragma unroll
    for (int o = 16; o; o >>= 1) m = fmaxf(m, __shfl_xor_sync(0xffffffffu, m, o));
    if (lane == 0) red[warp] = m;
    __syncthreads();
    if (tid == 0) {
        float mm = red[0];
        #pragma unroll
        for (int i = 1; i < 8; i++) mm = fmaxf(mm, red[i]);
        red[0] = mm;
    }
    __syncthreads();
    m = red[0];
    __syncthreads();

    float e = (tid < S_) ? __expf(v - m) : 0.f;
    float su = e;
    #pragma unroll
    for (int o = 16; o; o >>= 1) su += __shfl_xor_sync(0xffffffffu, su, o);
    if (lane == 0) red[warp] = su;
    __syncthreads();
    if (tid == 0) {
        float ss = 0.f;
        #pragma unroll
        for (int i = 0; i < 8; i++) ss += red[i];
        red[0] = ss;
    }
    __syncthreads();
    const float inv = 1.0f / red[0];
    if (tid < S_) {
        float wnorm = e * inv;
        ws[tid] = wnorm;
        if (rc == 0) weight_out[b * S_ + tid] = wnorm;
    }
    __syncthreads();

    // --- direct pooling: this thread's r column, all 196 s ---
    const int r = rc * 256 + tid;
    const float* af = att_feats + (size_t)b * S_ * R_ + r;
    float acc = 0.f;
    #pragma unroll 7
    for (int s = 0; s < S_; s++) {
        acc = fmaf(ws[s], af[(size_t)s * R_], acc);
    }
    att_res[(size_t)b * R_ + r] = acc;
}

// ---------------------------------------------------------------------------
extern "C" void kernel_launch(void* const* d_in, const int* in_sizes, int n_in,
                              void* d_out, int out_size) {
    const float* att_feats = (const float*)d_in[0];  // [B,S,R]
    const float* p_att     = (const float*)d_in[1];  // [B,S,H]
    const float* hidden    = (const float*)d_in[2];  // [B,R]
    const float* in_w      = (const float*)d_in[3];  // [B,S]
    const float* h2w       = (const float*)d_in[4];  // [H,R]
    const float* h2b       = (const float*)d_in[5];  // [H]
    const float* aw        = (const float*)d_in[6];  // [1,H]
    const float* ab        = (const float*)d_in[7];  // [1]

    float* out     = (float*)d_out;
    float* att_res = out;                 // [B,R]
    float* weight  = out + B_ * R_;       // [B,S]

    k_h2att <<<dim3(H_ / BN, B_ / BM, KSPLIT), 256>>>(hidden, h2w, h2b);
    k_scores<<<dim3(2, B_), 512>>>(p_att, in_w, aw, ab);
    k_pool  <<<dim3(4, B_), 256>>>(att_feats, weight, att_res);
}